// round 2
// baseline (speedup 1.0000x reference)
#include <cuda_runtime.h>
#include <cuda_bf16.h>

// Shapes (fixed by the problem)
#define BB 64      // batch
#define VV 64      // num nodes
#define DD 64      // input dim
#define HH 64      // hidden
#define EEDGES 4032
#define ETY 2
#define NJ 4       // receivers per block in msg_kernel

// Scratch: P[b][v][h] (recv-side partial, bias folded), QT[b][h][v] (send-side, transposed),
// W2T[h][o] = W2[1][o][h]
__device__ float g_P  [BB * VV * HH];
__device__ float g_QT [BB * HH * VV];
__device__ float g_W2T[HH * HH];

// ---------------------------------------------------------------------------
// Kernel A: per-node precompute.
//   P[b,v,h]  = sum_d inputs[b,v,d] * W1[1][h, d]       + b1[1][h]
//   QT[b,h,v] = sum_d inputs[b,v,d] * W1[1][h, 64+d]
// One block per (b, half). 64x64x64 GEMM, 8x4 register tile, 128 threads.
// ---------------------------------------------------------------------------
__global__ __launch_bounds__(128) void prep_kernel(
    const float* __restrict__ inputs,
    const float* __restrict__ W1,
    const float* __restrict__ b1)
{
    const int b    = blockIdx.x;
    const int half = blockIdx.y;   // 0 -> P (recv weights), 1 -> Q (send weights)
    const int t    = threadIdx.x;

    __shared__ float XT[64 * 65];  // XT[d][v]  (stride 65: conflict-free)
    __shared__ float WT[64 * 65];  // WT[d][h]  = W1[1][h][half*64+d]

    // Transposed load of inputs[b] (4096 floats)
    const float4* in4 = reinterpret_cast<const float4*>(inputs) + b * 1024;
    #pragma unroll
    for (int s = 0; s < 8; s++) {
        int item = t + 128 * s;            // 1024 float4
        int v = item >> 4, d4 = item & 15;
        float4 x = in4[v * 16 + d4];
        XT[(4 * d4 + 0) * 65 + v] = x.x;
        XT[(4 * d4 + 1) * 65 + v] = x.y;
        XT[(4 * d4 + 2) * 65 + v] = x.z;
        XT[(4 * d4 + 3) * 65 + v] = x.w;
    }
    // Transposed load of W1[1][:, half*64 : half*64+64]
    const float4* w14 = reinterpret_cast<const float4*>(W1);
    #pragma unroll
    for (int s = 0; s < 8; s++) {
        int item = t + 128 * s;
        int h = item >> 4, d4 = item & 15;
        float4 w = w14[2048 + h * 32 + half * 16 + d4]; // float off 8192 + h*128 + half*64 + 4*d4
        WT[(4 * d4 + 0) * 65 + h] = w.x;
        WT[(4 * d4 + 1) * 65 + h] = w.y;
        WT[(4 * d4 + 2) * 65 + h] = w.z;
        WT[(4 * d4 + 3) * 65 + h] = w.w;
    }
    __syncthreads();

    const int tx = t & 15, ty = t >> 4;    // ty in [0,8)
    const int r0 = ty * 8, k0 = tx * 4;    // rows = v, cols = h
    float acc[8][4];
    #pragma unroll
    for (int rr = 0; rr < 8; rr++)
        #pragma unroll
        for (int cc = 0; cc < 4; cc++) acc[rr][cc] = 0.f;

    #pragma unroll 4
    for (int kk = 0; kk < 64; kk++) {
        float a[8], bv[4];
        #pragma unroll
        for (int u = 0; u < 8; u++) a[u] = XT[kk * 65 + r0 + u];
        #pragma unroll
        for (int u = 0; u < 4; u++) bv[u] = WT[kk * 65 + k0 + u];
        #pragma unroll
        for (int rr = 0; rr < 8; rr++)
            #pragma unroll
            for (int cc = 0; cc < 4; cc++)
                acc[rr][cc] = fmaf(a[rr], bv[cc], acc[rr][cc]);
    }

    if (half == 0) {
        // P: direct store, fold bias b1[1][h]
        #pragma unroll
        for (int rr = 0; rr < 8; rr++) {
            int v = r0 + rr;
            #pragma unroll
            for (int cc = 0; cc < 4; cc++) {
                int h = k0 + cc;
                g_P[(b * 64 + v) * 64 + h] = acc[rr][cc] + b1[64 + h];
            }
        }
    } else {
        // Q: stage transposed in smem (reuse XT) then coalesced store to QT[b][h][v]
        __syncthreads();
        #pragma unroll
        for (int rr = 0; rr < 8; rr++)
            #pragma unroll
            for (int cc = 0; cc < 4; cc++)
                XT[(k0 + cc) * 65 + (r0 + rr)] = acc[rr][cc];
        __syncthreads();
        float* dst = g_QT + b * 4096;
        #pragma unroll
        for (int s = 0; s < 32; s++) {
            int idx = t + 128 * s;         // 4096 floats
            int h = idx >> 6, v = idx & 63;
            dst[idx] = XT[h * 65 + v];
        }
    }
}

// ---------------------------------------------------------------------------
// Tiny transpose: g_W2T[h][o] = W2[1][o][h]. One block, 256 threads.
// ---------------------------------------------------------------------------
__global__ __launch_bounds__(256) void transpose_w2(const float* __restrict__ W2)
{
    __shared__ float T[64 * 65];
    const int t = threadIdx.x;
    #pragma unroll
    for (int s = 0; s < 16; s++) {
        int idx = t + 256 * s;             // 4096
        int o = idx >> 6, h = idx & 63;
        T[h * 65 + o] = W2[4096 + idx];    // W2[1][o][h]
    }
    __syncthreads();
    #pragma unroll
    for (int s = 0; s < 16; s++) {
        int idx = t + 256 * s;
        int h = idx >> 6, o = idx & 63;
        g_W2T[idx] = T[h * 65 + o];
    }
}

// ---------------------------------------------------------------------------
// Kernel B: one block per (b, group of NJ receivers j).
//   HmT[h][r] = relu(P[b,j,h] + QT[b,h,i(r)])   (r: 63 senders, row 63 pad, ew=0)
//   C[r][o]   = sum_h HmT[h][r] * W2T[h][o]     (register-tiled, float4 smem loads)
//   agg[o]    = sum_r relu(C[r][o] + b2[1][o]) * ew[r]
//   out[b,j]  = [ inputs[b,j] | agg ]
// W2T and HmT live in XOR-swizzled stride-64 layouts (conflict-free float4 reads);
// QT[b] cached in smem (stride 68).
// ---------------------------------------------------------------------------
__global__ __launch_bounds__(128) void msg_kernel(
    const float* __restrict__ inputs,
    const float* __restrict__ edges,
    const float* __restrict__ b2,
    float* __restrict__ out)
{
    const int j0 = blockIdx.x * NJ;
    const int b  = blockIdx.y;
    const int t  = threadIdx.x;

    __shared__ __align__(16) float W2Ts[64 * 64];  // swizzled cells: [h][c ^ (h&15)]
    __shared__ __align__(16) float HmTs[64 * 64];  // swizzled cells: [h][c ^ (h&15)]
    __shared__ __align__(16) float QTs [64 * 68];  // QTs[h*68 + v]
    __shared__ float b2s[64], Ps[64], ews[64], red[8 * 64];

    float4* W2T4 = reinterpret_cast<float4*>(W2Ts);
    float4* HmT4 = reinterpret_cast<float4*>(HmTs);

    // Fill W2T (swizzled) — coalesced float4 both sides
    const float4* gw4 = reinterpret_cast<const float4*>(g_W2T);
    #pragma unroll
    for (int s = 0; s < 8; s++) {
        int item = t + 128 * s;            // 1024 float4 cells
        int h = item >> 4, c = item & 15;
        W2T4[h * 16 + (c ^ (h & 15))] = gw4[item];
    }
    // Fill QTs (stride 68) — coalesced float4 reads
    const float4* qt4 = reinterpret_cast<const float4*>(g_QT + b * 4096);
    #pragma unroll
    for (int s = 0; s < 8; s++) {
        int item = t + 128 * s;
        int h = item >> 4, v4 = item & 15;
        *reinterpret_cast<float4*>(&QTs[h * 68 + v4 * 4]) = qt4[item];
    }
    if (t < 64) b2s[t] = b2[64 + t];

    const int tx = t & 15, ty = t >> 4;
    const int r0 = ty * 8, k0 = tx * 4;
    const int ca = ty * 2;                 // a-cell (even), a1 = cell^1
    const int cb = tx;                     // b-cell

    for (int jj = 0; jj < NJ; jj++) {
        const int j = j0 + jj;
        if (t < 64) {
            Ps[t] = g_P[(b * 64 + j) * 64 + t];
            float w = 0.f;
            if (t < 63) {
                int i = t + (t >= j ? 1 : 0);
                int e = i * 63 + (j < i ? j : j - 1);
                w = __ldg(&edges[(b * EEDGES + e) * ETY + 1]);
            }
            ews[t] = w;
        }
        __syncthreads();   // Ps/ews ready; prior GEMM done -> HmT safe to rebuild

        // Build HmT (swizzled scalar writes, conflict-free)
        {
            int r = t & 63;
            int hb = t >> 6;                           // 0 or 1
            int i = (r < 63) ? (r + (r >= j ? 1 : 0)) : 0;  // pad row -> ew 0
            #pragma unroll
            for (int h = hb; h < 64; h += 2) {
                float v = Ps[h] + QTs[h * 68 + i];
                int cell = (r >> 2) ^ (h & 15);
                HmTs[(h * 16 + cell) * 4 + (r & 3)] = fmaxf(v, 0.f);
            }
        }
        __syncthreads();

        // GEMM: C[r][o], 8 rows x 4 cols per thread, float4 smem loads
        float acc[8][4];
        #pragma unroll
        for (int rr = 0; rr < 8; rr++)
            #pragma unroll
            for (int cc = 0; cc < 4; cc++) acc[rr][cc] = 0.f;

        #pragma unroll 8
        for (int kk = 0; kk < 64; kk++) {
            int s = kk & 15, base = kk * 16;
            float4 b4  = W2T4[base + (cb ^ s)];
            float4 a04 = HmT4[base + (ca ^ s)];
            float4 a14 = HmT4[base + ((ca ^ s) ^ 1)];
            float a[8] = {a04.x, a04.y, a04.z, a04.w, a14.x, a14.y, a14.z, a14.w};
            float bv[4] = {b4.x, b4.y, b4.z, b4.w};
            #pragma unroll
            for (int rr = 0; rr < 8; rr++)
                #pragma unroll
                for (int cc = 0; cc < 4; cc++)
                    acc[rr][cc] = fmaf(a[rr], bv[cc], acc[rr][cc]);
        }

        // Epilogue: relu + bias, edge-weight scale, partial row-reduce
        float part[4] = {0.f, 0.f, 0.f, 0.f};
        #pragma unroll
        for (int rr = 0; rr < 8; rr++) {
            float w = ews[r0 + rr];
            #pragma unroll
            for (int cc = 0; cc < 4; cc++)
                part[cc] += fmaxf(acc[rr][cc] + b2s[k0 + cc], 0.f) * w;
        }
        #pragma unroll
        for (int cc = 0; cc < 4; cc++)
            red[ty * 64 + k0 + cc] = part[cc];
        __syncthreads();

        // Final reduce + output write
        if (t < 64) {
            float sum = 0.f;
            #pragma unroll
            for (int u = 0; u < 8; u++) sum += red[u * 64 + t];
            float* orow = out + (b * 64 + j) * (DD + HH);
            orow[64 + t] = sum;                             // agg half
            orow[t]      = inputs[(b * 64 + j) * 64 + t];   // passthrough half
        }
    }
}

extern "C" void kernel_launch(void* const* d_in, const int* in_sizes, int n_in,
                              void* d_out, int out_size)
{
    const float* inputs = (const float*)d_in[0];
    const float* edges  = (const float*)d_in[1];
    const float* W1     = (const float*)d_in[2];
    const float* b1     = (const float*)d_in[3];
    const float* W2     = (const float*)d_in[4];
    const float* b2     = (const float*)d_in[5];
    // d_in[6]=send_idx, d_in[7]=recv_idx: complete-minus-diagonal, handled analytically
    float* out = (float*)d_out;

    transpose_w2<<<1, 256>>>(W2);
    dim3 gridA(BB, 2);
    prep_kernel<<<gridA, 128>>>(inputs, W1, b1);

    dim3 gridB(VV / NJ, BB);  // (j-group, b)
    msg_kernel<<<gridB, 128>>>(inputs, edges, b2, out);
}

// round 5
// speedup vs baseline: 1.9795x; 1.9795x over previous
#include <cuda_runtime.h>
#include <cuda_bf16.h>
#include <cstdint>

// Shapes (fixed by the problem)
#define BB 64      // batch
#define VV 64      // num nodes
#define DD 64      // input dim
#define HH 64      // hidden
#define EEDGES 4032
#define ETY 2
#define NJ 4       // receivers per block in msg_kernel

// Scratch:
//   g_P  [b][v][h]   recv-side partial, bias folded (plain layout)
//   g_Qp [b][v][32]  send-side partial, PAIR-PACKED: pair cp=(ks*4+tig) holds
//                    (Q[v][ks*8+tig], Q[v][ks*8+tig+4])
__device__ float  g_P [BB * VV * HH];
__device__ float2 g_Qp[BB * VV * 32];

// ---------------------------------------------------------------------------
// Kernel A: per-node precompute (fp32, exact).
//   P[b,v,h] = sum_d inputs[b,v,d] * W1[1][h, d]      + b1[1][h]
//   Q[b,v,h] = sum_d inputs[b,v,d] * W1[1][h, 64+d]   (stored pair-packed)
// One block per (b, half). 64x64x64 GEMM, 8x4 register tile, 128 threads.
// ---------------------------------------------------------------------------
__global__ __launch_bounds__(128) void prep_kernel(
    const float* __restrict__ inputs,
    const float* __restrict__ W1,
    const float* __restrict__ b1)
{
    const int b    = blockIdx.x;
    const int half = blockIdx.y;   // 0 -> P (recv weights), 1 -> Q (send weights)
    const int t    = threadIdx.x;

    __shared__ float XT[64 * 65];  // XT[d][v]
    __shared__ float WT[64 * 65];  // WT[d][h] = W1[1][h][half*64+d]

    const float4* in4 = reinterpret_cast<const float4*>(inputs) + b * 1024;
    #pragma unroll
    for (int s = 0; s < 8; s++) {
        int item = t + 128 * s;            // 1024 float4
        int v = item >> 4, d4 = item & 15;
        float4 x = in4[v * 16 + d4];
        XT[(4 * d4 + 0) * 65 + v] = x.x;
        XT[(4 * d4 + 1) * 65 + v] = x.y;
        XT[(4 * d4 + 2) * 65 + v] = x.z;
        XT[(4 * d4 + 3) * 65 + v] = x.w;
    }
    const float4* w14 = reinterpret_cast<const float4*>(W1);
    #pragma unroll
    for (int s = 0; s < 8; s++) {
        int item = t + 128 * s;
        int h = item >> 4, d4 = item & 15;
        float4 w = w14[2048 + h * 32 + half * 16 + d4]; // W1[1][h][half*64 + 4*d4]
        WT[(4 * d4 + 0) * 65 + h] = w.x;
        WT[(4 * d4 + 1) * 65 + h] = w.y;
        WT[(4 * d4 + 2) * 65 + h] = w.z;
        WT[(4 * d4 + 3) * 65 + h] = w.w;
    }
    __syncthreads();

    const int tx = t & 15, ty = t >> 4;
    const int r0 = ty * 8, k0 = tx * 4;    // rows = v, cols = h
    float acc[8][4];
    #pragma unroll
    for (int rr = 0; rr < 8; rr++)
        #pragma unroll
        for (int cc = 0; cc < 4; cc++) acc[rr][cc] = 0.f;

    #pragma unroll 4
    for (int kk = 0; kk < 64; kk++) {
        float a[8], bv[4];
        #pragma unroll
        for (int u = 0; u < 8; u++) a[u] = XT[kk * 65 + r0 + u];
        #pragma unroll
        for (int u = 0; u < 4; u++) bv[u] = WT[kk * 65 + k0 + u];
        #pragma unroll
        for (int rr = 0; rr < 8; rr++)
            #pragma unroll
            for (int cc = 0; cc < 4; cc++)
                acc[rr][cc] = fmaf(a[rr], bv[cc], acc[rr][cc]);
    }

    if (half == 0) {
        #pragma unroll
        for (int rr = 0; rr < 8; rr++) {
            int v = r0 + rr;
            #pragma unroll
            for (int cc = 0; cc < 4; cc++) {
                int h = k0 + cc;
                g_P[(b * 64 + v) * 64 + h] = acc[rr][cc] + b1[64 + h];
            }
        }
    } else {
        // Stage plain [v][h] in smem (reuse XT), then emit pair-packed
        __syncthreads();
        #pragma unroll
        for (int rr = 0; rr < 8; rr++)
            #pragma unroll
            for (int cc = 0; cc < 4; cc++)
                XT[(r0 + rr) * 65 + (k0 + cc)] = acc[rr][cc];
        __syncthreads();
        float2* dst = g_Qp + b * 2048;
        #pragma unroll
        for (int s = 0; s < 16; s++) {
            int idx = t + 128 * s;          // 2048 pairs
            int v = idx >> 5, cp = idx & 31;
            int h0 = (cp >> 2) * 8 + (cp & 3);
            dst[idx] = make_float2(XT[v * 65 + h0], XT[v * 65 + h0 + 4]);
        }
    }
}

// ---------------------------------------------------------------------------
// tf32 mma.sync m16n8k8 (row.col, fp32 accumulate)
// Fragment layout (cutlass SM80_16x8x8_F32TF32TF32F32_TN, re-derived):
//   A: a0=(g,tig) a1=(g+8,tig) a2=(g,tig+4) a3=(g+8,tig+4)
//   B: b0=(k=tig,n=g) b1=(k=tig+4,n=g)
//   C: c0=(g,2t) c1=(g,2t+1) c2=(g+8,2t) c3=(g+8,2t+1)
// ---------------------------------------------------------------------------
__device__ __forceinline__ void mma_tf32(
    float& c0, float& c1, float& c2, float& c3,
    uint32_t a0, uint32_t a1, uint32_t a2, uint32_t a3,
    uint32_t b0, uint32_t b1)
{
    asm volatile(
        "mma.sync.aligned.m16n8k8.row.col.f32.tf32.tf32.f32 "
        "{%0,%1,%2,%3},{%4,%5,%6,%7},{%8,%9},{%0,%1,%2,%3};"
        : "+f"(c0), "+f"(c1), "+f"(c2), "+f"(c3)
        : "r"(a0), "r"(a1), "r"(a2), "r"(a3), "r"(b0), "r"(b1));
}

__device__ __forceinline__ uint32_t f2tf32(float v)
{
    uint32_t r;
    asm("cvt.rna.tf32.f32 %0, %1;" : "=r"(r) : "f"(v));
    return r;
}

// ---------------------------------------------------------------------------
// Kernel B: one block (128 threads = 4 warps) per (b, group of NJ receivers).
// Pair-packed smem (stride 36 float2 => (g*36+tig) % 16 distinct per 16-lane
// phase => conflict-free LDS.64 fragment loads):
//   Hmp[r][cp]  = tf32 pair of relu(P[j,.] + Q[i(r),.])
//   W2p[o][cp]  = tf32 pair of W2[1][o][.]
//   Qsp[v][cp]  = Q pairs for this batch (fp32)
// GEMM C[r][o] via mma; epilogue relu(C+b2)*ew, row-reduce, out=[inputs|agg].
// ---------------------------------------------------------------------------
__global__ __launch_bounds__(128) void msg_kernel(
    const float* __restrict__ inputs,
    const float* __restrict__ edges,
    const float* __restrict__ W2,
    const float* __restrict__ b2,
    float* __restrict__ out)
{
    extern __shared__ __align__(16) char smraw[];
    float2* Hmp = reinterpret_cast<float2*>(smraw);          // 64*36
    float2* W2p = Hmp + 64 * 36;                             // 64*36
    float2* Qsp = W2p + 64 * 36;                             // 64*32
    float*  b2s = reinterpret_cast<float*>(Qsp + 64 * 32);   // 64
    float*  Ps  = b2s + 64;                                  // 64
    float*  ews = Ps  + 64;                                  // 64
    float*  red = ews + 64;                                  // 4*64

    const int j0 = blockIdx.x * NJ;
    const int b  = blockIdx.y;
    const int t  = threadIdx.x;
    const int w    = t >> 5;
    const int lane = t & 31;
    const int g    = lane >> 2;      // groupID
    const int tig  = lane & 3;       // thread-in-group
    const int rw   = w * 16;         // warp's row base

    // Fill W2p (tf32 pairs) — coalesced gmem reads, conflict-free smem
    #pragma unroll
    for (int s = 0; s < 16; s++) {
        int idx = t + 128 * s;                 // 2048 pairs
        int o = idx >> 5, cp = idx & 31;
        int h0 = (cp >> 2) * 8 + (cp & 3);
        const float* wrow = W2 + 4096 + o * 64;
        W2p[o * 36 + cp] = make_float2(
            __uint_as_float(f2tf32(wrow[h0])),
            __uint_as_float(f2tf32(wrow[h0 + 4])));
    }
    // Fill Qsp — float4 copy of pair-packed gmem
    {
        const float4* q4 = reinterpret_cast<const float4*>(g_Qp + b * 2048);
        float4* s4 = reinterpret_cast<float4*>(Qsp);
        #pragma unroll
        for (int s = 0; s < 8; s++) s4[t + 128 * s] = q4[t + 128 * s];
    }
    if (t < 64) b2s[t] = b2[64 + t];

    for (int jj = 0; jj < NJ; jj++) {
        const int j = j0 + jj;
        if (t < 64) {
            Ps[t] = g_P[(b * 64 + j) * 64 + t];
            float ew = 0.f;
            if (t < 63) {
                int i = t + (t >= j ? 1 : 0);
                int e = i * 63 + (j < i ? j : j - 1);
                ew = __ldg(&edges[(b * EEDGES + e) * ETY + 1]);
            }
            ews[t] = ew;
        }
        __syncthreads();   // S1: Ps/ews visible; prior GEMM done -> Hmp reusable

        // Build Hmp: warp w owns rows [w*16, w*16+16), lane owns pair cp=lane
        {
            const int cp = lane;
            const int h0 = (cp >> 2) * 8 + (cp & 3);
            const float p0 = Ps[h0], p1 = Ps[h0 + 4];
            #pragma unroll
            for (int rr = 0; rr < 16; rr++) {
                int r = rw + rr;
                int i = (r < 63) ? (r + (r >= j ? 1 : 0)) : 0;   // pad row -> ew 0
                float2 q = Qsp[i * 32 + cp];
                Hmp[r * 36 + cp] = make_float2(
                    __uint_as_float(f2tf32(fmaxf(p0 + q.x, 0.f))),
                    __uint_as_float(f2tf32(fmaxf(p1 + q.y, 0.f))));
            }
        }
        __syncthreads();   // S2: Hmp ready

        // GEMM: warp computes C[rw:rw+16][0:64]; 8 k-steps x 8 n-blocks
        float acc[8][4];
        #pragma unroll
        for (int nb = 0; nb < 8; nb++)
            #pragma unroll
            for (int cc = 0; cc < 4; cc++) acc[nb][cc] = 0.f;

        #pragma unroll
        for (int ks = 0; ks < 8; ks++) {
            const int pp = ks * 4 + tig;
            float2 aLo = Hmp[(rw + g) * 36 + pp];       // (a0, a2)
            float2 aHi = Hmp[(rw + g + 8) * 36 + pp];   // (a1, a3)
            uint32_t a0 = __float_as_uint(aLo.x);
            uint32_t a1 = __float_as_uint(aHi.x);
            uint32_t a2 = __float_as_uint(aLo.y);
            uint32_t a3 = __float_as_uint(aHi.y);
            #pragma unroll
            for (int nb = 0; nb < 8; nb++) {
                float2 bp = W2p[(nb * 8 + g) * 36 + pp];  // (b0, b1)
                mma_tf32(acc[nb][0], acc[nb][1], acc[nb][2], acc[nb][3],
                         a0, a1, a2, a3,
                         __float_as_uint(bp.x), __float_as_uint(bp.y));
            }
        }

        // Epilogue: relu(C + b2) * ew, reduce over rows
        float part[16];
        {
            const float w1 = ews[rw + g];
            const float w2 = ews[rw + g + 8];
            #pragma unroll
            for (int nb = 0; nb < 8; nb++) {
                #pragma unroll
                for (int cc = 0; cc < 2; cc++) {
                    int o = nb * 8 + 2 * tig + cc;
                    float bo = b2s[o];
                    float v1 = fmaxf(acc[nb][cc]     + bo, 0.f) * w1;
                    float v2 = fmaxf(acc[nb][2 + cc] + bo, 0.f) * w2;
                    part[nb * 2 + cc] = v1 + v2;
                }
            }
        }
        // shfl-tree over groupID: lanes 0..3 hold warp's column sums
        #pragma unroll
        for (int off = 16; off >= 4; off >>= 1)
            #pragma unroll
            for (int p = 0; p < 16; p++)
                part[p] += __shfl_down_sync(0xffffffffu, part[p], off);

        if (lane < 4) {
            #pragma unroll
            for (int nb = 0; nb < 8; nb++)
                #pragma unroll
                for (int cc = 0; cc < 2; cc++)
                    red[w * 64 + nb * 8 + 2 * lane + cc] = part[nb * 2 + cc];
        }
        __syncthreads();   // E: red visible; epilogue ews reads done

        if (t < 64) {
            float sum = red[t] + red[64 + t] + red[128 + t] + red[192 + t];
            float* orow = out + (b * 64 + j) * (DD + HH);
            orow[64 + t] = sum;                             // agg half
            orow[t]      = inputs[(b * 64 + j) * 64 + t];   // passthrough half
        }
    }
}

extern "C" void kernel_launch(void* const* d_in, const int* in_sizes, int n_in,
                              void* d_out, int out_size)
{
    const float* inputs = (const float*)d_in[0];
    const float* edges  = (const float*)d_in[1];
    const float* W1     = (const float*)d_in[2];
    const float* b1     = (const float*)d_in[3];
    const float* W2     = (const float*)d_in[4];
    const float* b2     = (const float*)d_in[5];
    // d_in[6]=send_idx, d_in[7]=recv_idx: complete-minus-diagonal, handled analytically
    float* out = (float*)d_out;

    const int smem_bytes = (64 * 36 * 2 + 64 * 32) * sizeof(float2)
                         + (64 * 3 + 256) * sizeof(float);
    cudaFuncSetAttribute(msg_kernel, cudaFuncAttributeMaxDynamicSharedMemorySize,
                         smem_bytes);

    dim3 gridA(BB, 2);
    prep_kernel<<<gridA, 128>>>(inputs, W1, b1);

    dim3 gridB(VV / NJ, BB);  // (j-group, b)
    msg_kernel<<<gridB, 128, smem_bytes>>>(inputs, edges, W2, b2, out);
}

// round 6
// speedup vs baseline: 2.2061x; 1.1145x over previous
#include <cuda_runtime.h>
#include <cuda_bf16.h>
#include <cstdint>

// Shapes (fixed by the problem)
#define BB 64      // batch
#define VV 64      // num nodes
#define DD 64      // input dim
#define HH 64      // hidden
#define EEDGES 4032
#define ETY 2
#define NJ 4       // receivers per block in msg_kernel

// Scratch:
//   g_P  [b][v][h]   recv-side partial, bias folded (plain layout)
//   g_Qp [b][v][32]  send-side partial, PAIR-PACKED: pair cp holds
//                    (Q[v][(cp>>2)*8+(cp&3)], Q[v][(cp>>2)*8+(cp&3)+4])
__device__ float  g_P [BB * VV * HH];
__device__ float2 g_Qp[BB * VV * 32];

// ---------------------------------------------------------------------------
// Kernel A: per-node precompute (fp32, exact).
//   P[b,v,h] = sum_d inputs[b,v,d] * W1[1][h, d]      + b1[1][h]
//   Q[b,v,h] = sum_d inputs[b,v,d] * W1[1][h, 64+d]   (stored pair-packed)
// ---------------------------------------------------------------------------
__global__ __launch_bounds__(128) void prep_kernel(
    const float* __restrict__ inputs,
    const float* __restrict__ W1,
    const float* __restrict__ b1)
{
    const int b    = blockIdx.x;
    const int half = blockIdx.y;   // 0 -> P, 1 -> Q
    const int t    = threadIdx.x;

    __shared__ float XT[64 * 65];  // XT[d][v]
    __shared__ float WT[64 * 65];  // WT[d][h] = W1[1][h][half*64+d]

    const float4* in4 = reinterpret_cast<const float4*>(inputs) + b * 1024;
    #pragma unroll
    for (int s = 0; s < 8; s++) {
        int item = t + 128 * s;            // 1024 float4
        int v = item >> 4, d4 = item & 15;
        float4 x = in4[v * 16 + d4];
        XT[(4 * d4 + 0) * 65 + v] = x.x;
        XT[(4 * d4 + 1) * 65 + v] = x.y;
        XT[(4 * d4 + 2) * 65 + v] = x.z;
        XT[(4 * d4 + 3) * 65 + v] = x.w;
    }
    const float4* w14 = reinterpret_cast<const float4*>(W1);
    #pragma unroll
    for (int s = 0; s < 8; s++) {
        int item = t + 128 * s;
        int h = item >> 4, d4 = item & 15;
        float4 w = w14[2048 + h * 32 + half * 16 + d4]; // W1[1][h][half*64 + 4*d4]
        WT[(4 * d4 + 0) * 65 + h] = w.x;
        WT[(4 * d4 + 1) * 65 + h] = w.y;
        WT[(4 * d4 + 2) * 65 + h] = w.z;
        WT[(4 * d4 + 3) * 65 + h] = w.w;
    }
    __syncthreads();

    const int tx = t & 15, ty = t >> 4;
    const int r0 = ty * 8, k0 = tx * 4;    // rows = v, cols = h
    float acc[8][4];
    #pragma unroll
    for (int rr = 0; rr < 8; rr++)
        #pragma unroll
        for (int cc = 0; cc < 4; cc++) acc[rr][cc] = 0.f;

    #pragma unroll 4
    for (int kk = 0; kk < 64; kk++) {
        float a[8], bv[4];
        #pragma unroll
        for (int u = 0; u < 8; u++) a[u] = XT[kk * 65 + r0 + u];
        #pragma unroll
        for (int u = 0; u < 4; u++) bv[u] = WT[kk * 65 + k0 + u];
        #pragma unroll
        for (int rr = 0; rr < 8; rr++)
            #pragma unroll
            for (int cc = 0; cc < 4; cc++)
                acc[rr][cc] = fmaf(a[rr], bv[cc], acc[rr][cc]);
    }

    if (half == 0) {
        #pragma unroll
        for (int rr = 0; rr < 8; rr++) {
            int v = r0 + rr;
            #pragma unroll
            for (int cc = 0; cc < 4; cc++) {
                int h = k0 + cc;
                g_P[(b * 64 + v) * 64 + h] = acc[rr][cc] + b1[64 + h];
            }
        }
    } else {
        // Stage plain [v][h] in smem (reuse XT), then emit pair-packed
        __syncthreads();
        #pragma unroll
        for (int rr = 0; rr < 8; rr++)
            #pragma unroll
            for (int cc = 0; cc < 4; cc++)
                XT[(r0 + rr) * 65 + (k0 + cc)] = acc[rr][cc];
        __syncthreads();
        float2* dst = g_Qp + b * 2048;
        #pragma unroll
        for (int s = 0; s < 16; s++) {
            int idx = t + 128 * s;          // 2048 pairs
            int v = idx >> 5, cp = idx & 31;
            int h0 = (cp >> 2) * 8 + (cp & 3);
            dst[idx] = make_float2(XT[v * 65 + h0], XT[v * 65 + h0 + 4]);
        }
    }
}

// ---------------------------------------------------------------------------
// tf32 mma.sync m16n8k8 (row.col, fp32 accumulate)
//   A: a0=(g,tig) a1=(g+8,tig) a2=(g,tig+4) a3=(g+8,tig+4)
//   B: b0=(k=tig,n=g) b1=(k=tig+4,n=g)
//   C: c0=(g,2t) c1=(g,2t+1) c2=(g+8,2t) c3=(g+8,2t+1)
// ---------------------------------------------------------------------------
__device__ __forceinline__ void mma_tf32(
    float& c0, float& c1, float& c2, float& c3,
    uint32_t a0, uint32_t a1, uint32_t a2, uint32_t a3,
    uint32_t b0, uint32_t b1)
{
    asm volatile(
        "mma.sync.aligned.m16n8k8.row.col.f32.tf32.tf32.f32 "
        "{%0,%1,%2,%3},{%4,%5,%6,%7},{%8,%9},{%0,%1,%2,%3};"
        : "+f"(c0), "+f"(c1), "+f"(c2), "+f"(c3)
        : "r"(a0), "r"(a1), "r"(a2), "r"(a3), "r"(b0), "r"(b1));
}

__device__ __forceinline__ uint32_t f2tf32(float v)
{
    uint32_t r;
    asm("cvt.rna.tf32.f32 %0, %1;" : "=r"(r) : "f"(v));
    return r;
}

// ---------------------------------------------------------------------------
// Kernel B: one block (128 threads = 4 warps) per (b, group of NJ receivers).
// Warp w computes C[0:64][16w:16w+16] (all rows, 16 cols): B fragments of W2
// are j-invariant and live in registers for the whole block (loaded once from
// gmem). A (Hm) lives in pair-packed smem, stride-36 float2 (conflict-free
// LDS.64). Qp rows are read straight from gmem (L2-resident) during the build.
// Epilogue: relu(C+b2)*ew, shfl row-reduce, direct gmem store (disjoint cols).
// ---------------------------------------------------------------------------
__global__ __launch_bounds__(128, 5) void msg_kernel(
    const float* __restrict__ inputs,
    const float* __restrict__ edges,
    const float* __restrict__ W2,
    const float* __restrict__ b2,
    float* __restrict__ out)
{
    __shared__ __align__(16) float2 Hmp[64 * 36];   // tf32 pairs of Hm
    __shared__ float Ps[2][64], ews[2][64];         // double-buffered per j

    const int j0 = blockIdx.x * NJ;
    const int b  = blockIdx.y;
    const int t  = threadIdx.x;
    const int w    = t >> 5;
    const int lane = t & 31;
    const int g    = lane >> 2;      // groupID
    const int tig  = lane & 3;       // thread-in-group

    // Load j-invariant W2 B-fragments and b2 into registers.
    // Warp w covers output cols o in [16w, 16w+16); nb selects the 8-col block.
    uint32_t breg[2][8][2];
    #pragma unroll
    for (int nb = 0; nb < 2; nb++) {
        const int o = 16 * w + nb * 8 + g;
        const float* wrow = W2 + 4096 + o * 64;
        #pragma unroll
        for (int ks = 0; ks < 8; ks++) {
            breg[nb][ks][0] = f2tf32(__ldg(&wrow[ks * 8 + tig]));
            breg[nb][ks][1] = f2tf32(__ldg(&wrow[ks * 8 + tig + 4]));
        }
    }
    float b2r[2][2];
    #pragma unroll
    for (int nb = 0; nb < 2; nb++)
        #pragma unroll
        for (int cc = 0; cc < 2; cc++)
            b2r[nb][cc] = __ldg(&b2[64 + 16 * w + nb * 8 + 2 * tig + cc]);

    const float2* qp = g_Qp + b * 2048;

    for (int jj = 0; jj < NJ; jj++) {
        const int j = j0 + jj;
        const int buf = jj & 1;

        // Phase W: per-j scalars + passthrough output (t<64)
        if (t < 64) {
            Ps[buf][t] = g_P[(b * 64 + j) * 64 + t];
            float ew = 0.f;
            if (t < 63) {
                int i = t + (t >= j ? 1 : 0);
                int e = i * 63 + (j < i ? j : j - 1);
                ew = __ldg(&edges[(b * EEDGES + e) * ETY + 1]);
            }
            ews[buf][t] = ew;
            out[(b * 64 + j) * (DD + HH) + t] = inputs[(b * 64 + j) * 64 + t];
        }
        __syncthreads();   // S1: Ps/ews visible; all warps done reading Hmp (prev j)

        // Build Hmp: warp w owns rows [16w,16w+16); lane owns pair cp=lane.
        {
            const int cp = lane;
            const int h0 = (cp >> 2) * 8 + (cp & 3);
            const float p0 = Ps[buf][h0], p1 = Ps[buf][h0 + 4];
            #pragma unroll
            for (int rr = 0; rr < 16; rr++) {
                int r = 16 * w + rr;
                int i = (r < 63) ? (r + (r >= j ? 1 : 0)) : 0;   // pad row -> ew 0
                float2 q = __ldg(&qp[i * 32 + cp]);
                Hmp[r * 36 + cp] = make_float2(
                    __uint_as_float(f2tf32(fmaxf(p0 + q.x, 0.f))),
                    __uint_as_float(f2tf32(fmaxf(p1 + q.y, 0.f))));
            }
        }
        __syncthreads();   // S2: Hmp ready

        // GEMM: C[0:64][16w:16w+16] via 8 k-steps x 4 m-blocks x 2 n-blocks
        float acc[4][2][4];
        #pragma unroll
        for (int mb = 0; mb < 4; mb++)
            #pragma unroll
            for (int nb = 0; nb < 2; nb++)
                #pragma unroll
                for (int cc = 0; cc < 4; cc++) acc[mb][nb][cc] = 0.f;

        #pragma unroll
        for (int ks = 0; ks < 8; ks++) {
            const int pp = ks * 4 + tig;
            #pragma unroll
            for (int mb = 0; mb < 4; mb++) {
                float2 aLo = Hmp[(16 * mb + g) * 36 + pp];       // (a0, a2)
                float2 aHi = Hmp[(16 * mb + 8 + g) * 36 + pp];   // (a1, a3)
                uint32_t a0 = __float_as_uint(aLo.x);
                uint32_t a1 = __float_as_uint(aHi.x);
                uint32_t a2 = __float_as_uint(aLo.y);
                uint32_t a3 = __float_as_uint(aHi.y);
                #pragma unroll
                for (int nb = 0; nb < 2; nb++)
                    mma_tf32(acc[mb][nb][0], acc[mb][nb][1],
                             acc[mb][nb][2], acc[mb][nb][3],
                             a0, a1, a2, a3,
                             breg[nb][ks][0], breg[nb][ks][1]);
            }
        }

        // Epilogue: relu(C + b2) * ew, reduce over all 64 rows
        float part[4] = {0.f, 0.f, 0.f, 0.f};
        #pragma unroll
        for (int mb = 0; mb < 4; mb++) {
            const float w1 = ews[buf][16 * mb + g];
            const float w2 = ews[buf][16 * mb + 8 + g];
            #pragma unroll
            for (int nb = 0; nb < 2; nb++)
                #pragma unroll
                for (int cc = 0; cc < 2; cc++) {
                    float bo = b2r[nb][cc];
                    part[nb * 2 + cc] +=
                        fmaxf(acc[mb][nb][cc]     + bo, 0.f) * w1 +
                        fmaxf(acc[mb][nb][2 + cc] + bo, 0.f) * w2;
                }
        }
        // shfl-tree over groupID: lanes 0..3 (tig) hold column sums
        #pragma unroll
        for (int off = 16; off >= 4; off >>= 1)
            #pragma unroll
            for (int p = 0; p < 4; p++)
                part[p] += __shfl_down_sync(0xffffffffu, part[p], off);

        if (lane < 4) {
            float* orow = out + (b * 64 + j) * (DD + HH) + 64 + 16 * w;
            #pragma unroll
            for (int nb = 0; nb < 2; nb++)
                #pragma unroll
                for (int cc = 0; cc < 2; cc++)
                    orow[nb * 8 + 2 * lane + cc] = part[nb * 2 + cc];
        }
        // No end-of-loop barrier: next j's Ps/ews use the other buffer; the
        // next S1 orders Hmp reuse; output writes are to disjoint addresses.
    }
}

extern "C" void kernel_launch(void* const* d_in, const int* in_sizes, int n_in,
                              void* d_out, int out_size)
{
    const float* inputs = (const float*)d_in[0];
    const float* edges  = (const float*)d_in[1];
    const float* W1     = (const float*)d_in[2];
    const float* b1     = (const float*)d_in[3];
    const float* W2     = (const float*)d_in[4];
    const float* b2     = (const float*)d_in[5];
    // d_in[6]=send_idx, d_in[7]=recv_idx: complete-minus-diagonal, handled analytically
    float* out = (float*)d_out;

    dim3 gridA(BB, 2);
    prep_kernel<<<gridA, 128>>>(inputs, W1, b1);

    dim3 gridB(VV / NJ, BB);  // (j-group, b)
    msg_kernel<<<gridB, 128>>>(inputs, edges, W2, b2, out);
}

// round 10
// speedup vs baseline: 2.3689x; 1.0738x over previous
#include <cuda_runtime.h>
#include <cuda_bf16.h>
#include <cstdint>

// Shapes (fixed by the problem)
#define BB 64      // batch
#define VV 64      // num nodes
#define DD 64      // input dim
#define HH 64      // hidden
#define EEDGES 4032
#define ETY 2
#define NJ 8       // receivers per block in msg_kernel (grid = 512 -> single wave)

// Scratch:
//   g_P  [b][v][h]   recv-side partial, bias folded (plain layout)
//   g_Qp [b][v][32]  send-side partial, PAIR-PACKED: pair cp holds
//                    (Q[v][(cp>>2)*8+(cp&3)], Q[v][(cp>>2)*8+(cp&3)+4])
__device__ float  g_P [BB * VV * HH];
__device__ float2 g_Qp[BB * VV * 32];

// ---------------------------------------------------------------------------
// Kernel A: per-node precompute (fp32, exact).
//   P[b,v,h] = sum_d inputs[b,v,d] * W1[1][h, d]      + b1[1][h]
//   Q[b,v,h] = sum_d inputs[b,v,d] * W1[1][h, 64+d]   (stored pair-packed)
// ---------------------------------------------------------------------------
__global__ __launch_bounds__(128) void prep_kernel(
    const float* __restrict__ inputs,
    const float* __restrict__ W1,
    const float* __restrict__ b1)
{
    const int b    = blockIdx.x;
    const int half = blockIdx.y;   // 0 -> P, 1 -> Q
    const int t    = threadIdx.x;

    __shared__ float XT[64 * 65];  // XT[d][v]
    __shared__ float WT[64 * 65];  // WT[d][h] = W1[1][h][half*64+d]

    const float4* in4 = reinterpret_cast<const float4*>(inputs) + b * 1024;
    #pragma unroll
    for (int s = 0; s < 8; s++) {
        int item = t + 128 * s;            // 1024 float4
        int v = item >> 4, d4 = item & 15;
        float4 x = in4[v * 16 + d4];
        XT[(4 * d4 + 0) * 65 + v] = x.x;
        XT[(4 * d4 + 1) * 65 + v] = x.y;
        XT[(4 * d4 + 2) * 65 + v] = x.z;
        XT[(4 * d4 + 3) * 65 + v] = x.w;
    }
    const float4* w14 = reinterpret_cast<const float4*>(W1);
    #pragma unroll
    for (int s = 0; s < 8; s++) {
        int item = t + 128 * s;
        int h = item >> 4, d4 = item & 15;
        float4 w = w14[2048 + h * 32 + half * 16 + d4]; // W1[1][h][half*64 + 4*d4]
        WT[(4 * d4 + 0) * 65 + h] = w.x;
        WT[(4 * d4 + 1) * 65 + h] = w.y;
        WT[(4 * d4 + 2) * 65 + h] = w.z;
        WT[(4 * d4 + 3) * 65 + h] = w.w;
    }
    __syncthreads();

    const int tx = t & 15, ty = t >> 4;
    const int r0 = ty * 8, k0 = tx * 4;    // rows = v, cols = h
    float acc[8][4];
    #pragma unroll
    for (int rr = 0; rr < 8; rr++)
        #pragma unroll
        for (int cc = 0; cc < 4; cc++) acc[rr][cc] = 0.f;

    #pragma unroll 4
    for (int kk = 0; kk < 64; kk++) {
        float a[8], bv[4];
        #pragma unroll
        for (int u = 0; u < 8; u++) a[u] = XT[kk * 65 + r0 + u];
        #pragma unroll
        for (int u = 0; u < 4; u++) bv[u] = WT[kk * 65 + k0 + u];
        #pragma unroll
        for (int rr = 0; rr < 8; rr++)
            #pragma unroll
            for (int cc = 0; cc < 4; cc++)
                acc[rr][cc] = fmaf(a[rr], bv[cc], acc[rr][cc]);
    }

    if (half == 0) {
        #pragma unroll
        for (int rr = 0; rr < 8; rr++) {
            int v = r0 + rr;
            #pragma unroll
            for (int cc = 0; cc < 4; cc++) {
                int h = k0 + cc;
                g_P[(b * 64 + v) * 64 + h] = acc[rr][cc] + b1[64 + h];
            }
        }
    } else {
        // Stage plain [v][h] in smem (reuse XT), then emit pair-packed
        __syncthreads();
        #pragma unroll
        for (int rr = 0; rr < 8; rr++)
            #pragma unroll
            for (int cc = 0; cc < 4; cc++)
                XT[(r0 + rr) * 65 + (k0 + cc)] = acc[rr][cc];
        __syncthreads();
        float2* dst = g_Qp + b * 2048;
        #pragma unroll
        for (int s = 0; s < 16; s++) {
            int idx = t + 128 * s;          // 2048 pairs
            int v = idx >> 5, cp = idx & 31;
            int h0 = (cp >> 2) * 8 + (cp & 3);
            dst[idx] = make_float2(XT[v * 65 + h0], XT[v * 65 + h0 + 4]);
        }
    }
}

// ---------------------------------------------------------------------------
// tf32 mma.sync m16n8k8 (row.col, fp32 accumulate)
//   A: a0=(g,tig) a1=(g+8,tig) a2=(g,tig+4) a3=(g+8,tig+4)
//   B: b0=(k=tig,n=g) b1=(k=tig+4,n=g)
//   C: c0=(g,2t) c1=(g,2t+1) c2=(g+8,2t) c3=(g+8,2t+1)
// A operands carry raw fp32 bit patterns; HMMA.TF32 uses only the tf32 bits
// (truncation) — same mechanism the 3xTF32 decomposition relies on. B stays
// rna-rounded (one-time) to keep the coherent chop bias one-sided (~2e-4).
// ---------------------------------------------------------------------------
__device__ __forceinline__ void mma_tf32(
    float& c0, float& c1, float& c2, float& c3,
    uint32_t a0, uint32_t a1, uint32_t a2, uint32_t a3,
    uint32_t b0, uint32_t b1)
{
    asm volatile(
        "mma.sync.aligned.m16n8k8.row.col.f32.tf32.tf32.f32 "
        "{%0,%1,%2,%3},{%4,%5,%6,%7},{%8,%9},{%0,%1,%2,%3};"
        : "+f"(c0), "+f"(c1), "+f"(c2), "+f"(c3)
        : "r"(a0), "r"(a1), "r"(a2), "r"(a3), "r"(b0), "r"(b1));
}

__device__ __forceinline__ uint32_t f2tf32(float v)
{
    uint32_t r;
    asm("cvt.rna.tf32.f32 %0, %1;" : "=r"(r) : "f"(v));
    return r;
}

// Packed fp32 pair add (ptxas never auto-fuses this from C++)
__device__ __forceinline__ float2 add_f32x2(float2 a, float2 b)
{
    unsigned long long r, x, y;
    x = *reinterpret_cast<unsigned long long*>(&a);
    y = *reinterpret_cast<unsigned long long*>(&b);
    asm("add.rn.f32x2 %0, %1, %2;" : "=l"(r) : "l"(x), "l"(y));
    return *reinterpret_cast<float2*>(&r);
}

// ---------------------------------------------------------------------------
// Kernel B: one block (128 threads = 4 warps) per (b, group of NJ receivers).
// Warp w computes C[0:64][16w:16w+16]; W2 B-fragments are j-invariant and live
// in registers. Hm lives in pair-packed smem (stride-36 float2, conflict-free
// LDS.64). Per-j scalars (P row, edge weights, passthrough inputs) are
// register-prefetched during the previous GEMM. Epilogue: relu(C+b2)*ew, shfl
// row-reduce, direct gmem store.
// ---------------------------------------------------------------------------
__global__ __launch_bounds__(128, 5) void msg_kernel(
    const float* __restrict__ inputs,
    const float* __restrict__ edges,
    const float* __restrict__ W2,
    const float* __restrict__ b2,
    float* __restrict__ out)
{
    __shared__ __align__(16) float2 Hmp[64 * 36];   // Hm pairs (raw fp32)
    __shared__ float Ps[2][64], ews[2][64];         // double-buffered per j

    const int j0 = blockIdx.x * NJ;
    const int b  = blockIdx.y;
    const int t  = threadIdx.x;
    const int w    = t >> 5;
    const int lane = t & 31;
    const int g    = lane >> 2;      // groupID
    const int tig  = lane & 3;       // thread-in-group

    // j-invariant W2 B-fragments (rna tf32, one-time) and b2 in registers.
    uint32_t breg[2][8][2];
    #pragma unroll
    for (int nb = 0; nb < 2; nb++) {
        const int o = 16 * w + nb * 8 + g;
        const float* wrow = W2 + 4096 + o * 64;
        #pragma unroll
        for (int ks = 0; ks < 8; ks++) {
            breg[nb][ks][0] = f2tf32(__ldg(&wrow[ks * 8 + tig]));
            breg[nb][ks][1] = f2tf32(__ldg(&wrow[ks * 8 + tig + 4]));
        }
    }
    float b2r[2][2];
    #pragma unroll
    for (int nb = 0; nb < 2; nb++)
        #pragma unroll
        for (int cc = 0; cc < 2; cc++)
            b2r[nb][cc] = __ldg(&b2[64 + 16 * w + nb * 8 + 2 * tig + cc]);

    const float2* qp = g_Qp + b * 2048;

    // Prologue prefetch of j0's scalars (overlaps breg loads)
    float rP = 0.f, rEw = 0.f, rInp = 0.f;
    if (t < 64) {
        rP   = g_P[(b * 64 + j0) * 64 + t];
        rInp = inputs[(b * 64 + j0) * 64 + t];
        if (t < 63) {
            int i = t + (t >= j0 ? 1 : 0);
            int e = i * 63 + (j0 < i ? j0 : j0 - 1);
            rEw = __ldg(&edges[(b * EEDGES + e) * ETY + 1]);
        }
    }

    for (int jj = 0; jj < NJ; jj++) {
        const int j = j0 + jj;
        const int buf = jj & 1;

        if (t < 64) {                      // commit prefetched scalars
            Ps[buf][t]  = rP;
            ews[buf][t] = rEw;
        }
        __syncthreads();   // S1: scalars visible; all warps done with Hmp (prev j)

        // Build Hmp: warp w owns rows [16w,16w+16); lane owns pair cp=lane.
        {
            const int cp = lane;
            const int h0 = (cp >> 2) * 8 + (cp & 3);
            const float2 p = make_float2(Ps[buf][h0], Ps[buf][h0 + 4]);
            #pragma unroll
            for (int rr = 0; rr < 16; rr++) {
                int r = 16 * w + rr;
                int i = (r < 63) ? (r + (r >= j ? 1 : 0)) : 0;   // pad row -> ew 0
                float2 s = add_f32x2(p, __ldg(&qp[i * 32 + cp]));
                Hmp[r * 36 + cp] = make_float2(fmaxf(s.x, 0.f), fmaxf(s.y, 0.f));
            }
        }
        __syncthreads();   // S2: Hmp ready

        // Passthrough write + prefetch next j (LDG latency overlaps GEMM)
        if (t < 64) {
            out[(b * 64 + j) * (DD + HH) + t] = rInp;
            if (jj + 1 < NJ) {
                const int jn = j + 1;
                rP   = g_P[(b * 64 + jn) * 64 + t];
                rInp = inputs[(b * 64 + jn) * 64 + t];
                rEw = 0.f;
                if (t < 63) {
                    int i = t + (t >= jn ? 1 : 0);
                    int e = i * 63 + (jn < i ? jn : jn - 1);
                    rEw = __ldg(&edges[(b * EEDGES + e) * ETY + 1]);
                }
            }
        }

        // GEMM: C[0:64][16w:16w+16] via 8 k-steps x 4 m-blocks x 2 n-blocks
        float acc[4][2][4];
        #pragma unroll
        for (int mb = 0; mb < 4; mb++)
            #pragma unroll
            for (int nb = 0; nb < 2; nb++)
                #pragma unroll
                for (int cc = 0; cc < 4; cc++) acc[mb][nb][cc] = 0.f;

        #pragma unroll
        for (int ks = 0; ks < 8; ks++) {
            const int pp = ks * 4 + tig;
            #pragma unroll
            for (int mb = 0; mb < 4; mb++) {
                float2 aLo = Hmp[(16 * mb + g) * 36 + pp];       // (a0, a2)
                float2 aHi = Hmp[(16 * mb + 8 + g) * 36 + pp];   // (a1, a3)
                uint32_t a0 = __float_as_uint(aLo.x);
                uint32_t a1 = __float_as_uint(aHi.x);
                uint32_t a2 = __float_as_uint(aLo.y);
                uint32_t a3 = __float_as_uint(aHi.y);
                #pragma unroll
                for (int nb = 0; nb < 2; nb++)
                    mma_tf32(acc[mb][nb][0], acc[mb][nb][1],
                             acc[mb][nb][2], acc[mb][nb][3],
                             a0, a1, a2, a3,
                             breg[nb][ks][0], breg[nb][ks][1]);
            }
        }

        // Epilogue: relu(C + b2) * ew, reduce over all 64 rows
        float part[4] = {0.f, 0.f, 0.f, 0.f};
        #pragma unroll
        for (int mb = 0; mb < 4; mb++) {
            const float w1 = ews[buf][16 * mb + g];
            const float w2 = ews[buf][16 * mb + 8 + g];
            #pragma unroll
            for (int nb = 0; nb < 2; nb++)
                #pragma unroll
                for (int cc = 0; cc < 2; cc++) {
                    float bo = b2r[nb][cc];
                    part[nb * 2 + cc] +=
                        fmaxf(acc[mb][nb][cc]     + bo, 0.f) * w1 +
                        fmaxf(acc[mb][nb][2 + cc] + bo, 0.f) * w2;
                }
        }
        // shfl-tree over groupID: lanes 0..3 (tig) hold column sums
        #pragma unroll
        for (int off = 16; off >= 4; off >>= 1)
            #pragma unroll
            for (int p = 0; p < 4; p++)
                part[p] += __shfl_down_sync(0xffffffffu, part[p], off);

        if (lane < 4) {
            float* orow = out + (b * 64 + j) * (DD + HH) + 64 + 16 * w;
            #pragma unroll
            for (int nb = 0; nb < 2; nb++)
                #pragma unroll
                for (int cc = 0; cc < 2; cc++)
                    orow[nb * 8 + 2 * lane + cc] = part[nb * 2 + cc];
        }
        // No trailing barrier: next S1 orders Hmp reuse; scalar buffers alternate.
    }
}

extern "C" void kernel_launch(void* const* d_in, const int* in_sizes, int n_in,
                              void* d_out, int out_size)
{
    const float* inputs = (const float*)d_in[0];
    const float* edges  = (const float*)d_in[1];
    const float* W1     = (const float*)d_in[2];
    const float* b1     = (const float*)d_in[3];
    const float* W2     = (const float*)d_in[4];
    const float* b2     = (const float*)d_in[5];
    // d_in[6]=send_idx, d_in[7]=recv_idx: complete-minus-diagonal, handled analytically
    float* out = (float*)d_out;

    dim3 gridA(BB, 2);
    prep_kernel<<<gridA, 128>>>(inputs, W1, b1);

    dim3 gridB(VV / NJ, BB);  // (j-group, b) = (8, 64) = 512 blocks
    msg_kernel<<<gridB, 128>>>(inputs, edges, W2, b2, out);
}